// round 2
// baseline (speedup 1.0000x reference)
#include <cuda_runtime.h>
#include <cuda_bf16.h>

// TactileSpikeEncoder: bit-exact JAX threefry2x32 (partitionable) spike encoder.
// R2: alu-pipe was the bottleneck (all threefry ops on alu @2/cyc/SM).
//     Force all adds onto the fma pipe via IMAD; precompute 8 injection
//     constants per t; fuse threshold computation into k_rng.
// Pipeline: k_init (keys+consts, zero potOcc) -> k_rng (thresh+RNG+potOcc)
//        -> k_scan (refractory recurrence) -> k_out (gate & expand)

#define TT      100
#define NNEUR   256
#define TOTAL   524288   // 32*64*256
#define NBLK    2048     // TOTAL/256

__device__ uint4    g_keyc[TT * 2];         // per t: {k0,k1,k2,k2+1},{k0+2,k1+3,k2+4,k0+5}
__device__ uint4    g_sbits[TOTAL];         // 100-bit candidate mask per element (8 MB)
__device__ unsigned g_potOcc[NNEUR * 4];    // OR over (b,f) of candidate bits, per neuron
__device__ unsigned g_gate[NNEUR * 4];      // active (ref==0) mask per neuron
__device__ unsigned g_one;                  // runtime 1 (defeats const-folding of IMAD)

// Add on the FMA pipe: mad.lo.u32 d = a*one + b  ->  IMAD (fma pipe),
// freeing the alu pipe (SHF/LOP3) which is the throughput bottleneck.
__device__ __forceinline__ unsigned addf(unsigned a, unsigned b, unsigned one) {
    unsigned d;
    asm("mad.lo.u32 %0, %1, %2, %3;" : "=r"(d) : "r"(a), "r"(one), "r"(b));
    return d;
}

#define TF_ROUND(x0, x1, R)                    \
    x0 = addf(x0, x1, one);                    \
    x1 = __funnelshift_l(x1, x1, R);           \
    x1 ^= x0;

// plain version for k_init (cold path)
__device__ __forceinline__ void tf_g4p(unsigned &x0, unsigned &x1,
                                       int r0, int r1, int r2, int r3) {
    x0 += x1; x1 = __funnelshift_l(x1, x1, r0); x1 ^= x0;
    x0 += x1; x1 = __funnelshift_l(x1, x1, r1); x1 ^= x0;
    x0 += x1; x1 = __funnelshift_l(x1, x1, r2); x1 ^= x0;
    x0 += x1; x1 = __funnelshift_l(x1, x1, r3); x1 ^= x0;
}
__device__ __forceinline__ void tf2x32_plain(unsigned k0, unsigned k1, unsigned k2,
                                             unsigned &x0, unsigned &x1) {
    x0 += k0; x1 += k1;
    tf_g4p(x0, x1, 13, 15, 26, 6);
    x0 += k1; x1 += k2 + 1u;
    tf_g4p(x0, x1, 17, 29, 16, 24);
    x0 += k2; x1 += k0 + 2u;
    tf_g4p(x0, x1, 13, 15, 26, 6);
    x0 += k0; x1 += k1 + 3u;
    tf_g4p(x0, x1, 17, 29, 16, 24);
    x0 += k1; x1 += k2 + 4u;
    tf_g4p(x0, x1, 13, 15, 26, 6);
    x0 += k2; x1 += k0 + 5u;
}

// Per-timestep derived keys (fold_in) + injection-constant table + potOcc zero.
__global__ void k_init(const int* __restrict__ seedp) {
    int t = threadIdx.x;
    unsigned s = (unsigned)seedp[0];
    if (t < TT) {
        unsigned k0 = 0u, k1 = s;
        unsigned k2 = k0 ^ k1 ^ 0x1BD11BDAu;
        unsigned x0 = 0u, x1 = (unsigned)t;
        tf2x32_plain(k0, k1, k2, x0, x1);
        unsigned K0 = x0, K1 = x1;
        unsigned K2 = K0 ^ K1 ^ 0x1BD11BDAu;
        g_keyc[2 * t + 0] = make_uint4(K0, K1, K2, K2 + 1u);
        g_keyc[2 * t + 1] = make_uint4(K0 + 2u, K1 + 3u, K2 + 4u, K0 + 5u);
    }
    for (int q = t; q < NNEUR * 4; q += blockDim.x) g_potOcc[q] = 0u;
    if (t == 0) g_one = 1u;
}

// Hot kernel: threshold (fused) + 100 threefry blocks per element.
// Block b covers element pair bf=b (x value uniform per block), neuron n = tid.
__global__ void __launch_bounds__(256) k_rng(const float* __restrict__ x,
                                             const float* __restrict__ centers,
                                             const float* __restrict__ widths,
                                             const float* __restrict__ adapt) {
    __shared__ uint4 sk[TT * 2];
    int tid = threadIdx.x;
    if (tid < TT * 2) sk[tid] = g_keyc[tid];
    __syncthreads();

    unsigned i = blockIdx.x * 256u + tid;
    unsigned one = g_one;

    // Threshold: identical float op order to the validated reference path.
    {
        float xv = x[blockIdx.x];
        float c = centers[tid];
        float w = widths[tid];
        float d = xv - c;
        float num = -(d * d);
        float den = (2.0f * w) * w;
        float resp = expf(num / den);
        resp = resp * adapt[tid];
        float p = resp * 0.1f;
        // (bits>>9) < T  <=>  bits < (T<<9)   (T < 2^20, exact)
        unsigned T = (unsigned)ceilf(p * 8388608.0f);
        one = one; // keep 'one' live
        // store shifted threshold in a register
        // (fall through below)
        unsigned Tsh = T << 9;

        unsigned mask[4];
#pragma unroll
        for (int w4 = 0; w4 < 4; w4++) {
            unsigned mw = 0u;
            const int nb = (w4 < 3) ? 32 : 4;
#pragma unroll 4
            for (int b = 0; b < nb; b++) {
                int t = w4 * 32 + b;
                uint4 c1 = sk[2 * t + 0];
                uint4 c2 = sk[2 * t + 1];
                unsigned x0 = c1.x;                  // 0 + k0
                unsigned x1 = addf(i, c1.y, one);    // i + k1
                TF_ROUND(x0, x1, 13) TF_ROUND(x0, x1, 15)
                TF_ROUND(x0, x1, 26) TF_ROUND(x0, x1, 6)
                x0 = addf(x0, c1.y, one); x1 = addf(x1, c1.w, one); // +k1, +k2+1
                TF_ROUND(x0, x1, 17) TF_ROUND(x0, x1, 29)
                TF_ROUND(x0, x1, 16) TF_ROUND(x0, x1, 24)
                x0 = addf(x0, c1.z, one); x1 = addf(x1, c2.x, one); // +k2, +k0+2
                TF_ROUND(x0, x1, 13) TF_ROUND(x0, x1, 15)
                TF_ROUND(x0, x1, 26) TF_ROUND(x0, x1, 6)
                x0 = addf(x0, c1.x, one); x1 = addf(x1, c2.y, one); // +k0, +k1+3
                TF_ROUND(x0, x1, 17) TF_ROUND(x0, x1, 29)
                TF_ROUND(x0, x1, 16) TF_ROUND(x0, x1, 24)
                x0 = addf(x0, c1.y, one); x1 = addf(x1, c2.z, one); // +k1, +k2+4
                TF_ROUND(x0, x1, 13) TF_ROUND(x0, x1, 15)
                TF_ROUND(x0, x1, 26) TF_ROUND(x0, x1, 6)
                x0 = addf(x0, c1.z, one); x1 = addf(x1, c2.w, one); // +k2, +k0+5
                unsigned bits = x0 ^ x1;
                mw |= (bits < Tsh) ? (1u << b) : 0u;
            }
            mask[w4] = mw;
        }

        g_sbits[i] = make_uint4(mask[0], mask[1], mask[2], mask[3]);

        if (mask[0]) atomicOr(&g_potOcc[tid * 4 + 0], mask[0]);
        if (mask[1]) atomicOr(&g_potOcc[tid * 4 + 1], mask[1]);
        if (mask[2]) atomicOr(&g_potOcc[tid * 4 + 2], mask[2]);
        if (mask[3]) atomicOr(&g_potOcc[tid * 4 + 3], mask[3]);
    }
}

// Refractory recurrence per neuron (serial-latency bound, tiny).
__global__ void k_scan(const float* __restrict__ refr) {
    int n = threadIdx.x;
    unsigned p0 = g_potOcc[n * 4 + 0], p1 = g_potOcc[n * 4 + 1];
    unsigned p2 = g_potOcc[n * 4 + 2], p3 = g_potOcc[n * 4 + 3];
    float ref = refr[n];
    unsigned g0 = 0u, g1 = 0u, g2 = 0u, g3 = 0u;
#pragma unroll
    for (int t = 0; t < TT; t++) {
        unsigned pw = (t < 32) ? p0 : ((t < 64) ? p1 : ((t < 96) ? p2 : p3));
        bool active = (ref == 0.0f);
        unsigned bit = (pw >> (t & 31)) & 1u;
        unsigned occ = active ? bit : 0u;
        unsigned gbit = active ? 1u : 0u;
        if (t < 32)      g0 |= gbit << t;
        else if (t < 64) g1 |= gbit << (t - 32);
        else if (t < 96) g2 |= gbit << (t - 64);
        else             g3 |= gbit << (t - 96);
        ref = fmaxf(ref - 1.0f, 0.0f) + 2.0f * (float)occ;
    }
    g_gate[n * 4 + 0] = g0; g_gate[n * 4 + 1] = g1;
    g_gate[n * 4 + 2] = g2; g_gate[n * 4 + 3] = g3;
}

// Gate & expand to float32 output [B,F,N,T]; pure-bandwidth (210 MB writes).
__global__ void __launch_bounds__(256) k_out(float* __restrict__ out) {
    unsigned i = blockIdx.x * 256u + threadIdx.x;
    int n = threadIdx.x;
    uint4 s = g_sbits[i];
    unsigned w0 = s.x & g_gate[n * 4 + 0];
    unsigned w1 = s.y & g_gate[n * 4 + 1];
    unsigned w2 = s.z & g_gate[n * 4 + 2];
    unsigned w3 = s.w & g_gate[n * 4 + 3];

    float4* o = reinterpret_cast<float4*>(out + (size_t)i * TT);
#pragma unroll
    for (int q = 0; q < 25; q++) {
        int t0 = q * 4;
        unsigned word = (t0 < 32) ? w0 : ((t0 < 64) ? w1 : ((t0 < 96) ? w2 : w3));
        int sh = t0 & 31;
        float4 v;
        v.x = ((word >> (sh + 0)) & 1u) ? 1.0f : 0.0f;
        v.y = ((word >> (sh + 1)) & 1u) ? 1.0f : 0.0f;
        v.z = ((word >> (sh + 2)) & 1u) ? 1.0f : 0.0f;
        v.w = ((word >> (sh + 3)) & 1u) ? 1.0f : 0.0f;
        __stcs(&o[q], v);
    }
}

extern "C" void kernel_launch(void* const* d_in, const int* in_sizes, int n_in,
                              void* d_out, int out_size) {
    (void)in_sizes; (void)n_in; (void)out_size;
    const float* x       = (const float*)d_in[0];
    const float* centers = (const float*)d_in[1];
    const float* widths  = (const float*)d_in[2];
    const float* adapt   = (const float*)d_in[3];
    const float* refr    = (const float*)d_in[4];
    const int*   seed    = (const int*)d_in[5];
    float* out = (float*)d_out;

    k_init<<<1, 256>>>(seed);
    k_rng <<<NBLK, 256>>>(x, centers, widths, adapt);
    k_scan<<<1, NNEUR>>>(refr);
    k_out <<<NBLK, 256>>>(out);
}

// round 4
// speedup vs baseline: 1.4920x; 1.4920x over previous
#include <cuda_runtime.h>
#include <cuda_bf16.h>

// TactileSpikeEncoder: bit-exact JAX threefry2x32 (partitionable) spike encoder.
// R4: fix R3's pair-packing shift bug (u6: <<28 -> <<4). k_out writes
//     coalesced 1KB/warp via byte->2xfloat4 smem LUT.
// Pipeline: k_init -> k_rng (thresh+RNG+potOcc) -> k_scan -> k_out

#define TT      100
#define NNEUR   256
#define TOTAL   524288   // 32*64*256
#define NBLK    2048

__device__ uint4    g_keyc[TT * 2];         // per t: {k0,k1,k2,k2+1},{k0+2,k1+3,k2+4,k0+5}
__device__ uint4    g_sbits[TOTAL];         // 100-bit candidate mask per element (8 MB)
__device__ unsigned g_potOcc[NNEUR * 4];
__device__ unsigned g_gate[NNEUR * 4];
__device__ unsigned g_one;

__device__ __forceinline__ unsigned addf(unsigned a, unsigned b, unsigned one) {
    unsigned d;
    asm("mad.lo.u32 %0, %1, %2, %3;" : "=r"(d) : "r"(a), "r"(one), "r"(b));
    return d;
}

#define TF_ROUND(x0, x1, R)                    \
    x0 = addf(x0, x1, one);                    \
    x1 = __funnelshift_l(x1, x1, R);           \
    x1 ^= x0;

__device__ __forceinline__ void tf_g4p(unsigned &x0, unsigned &x1,
                                       int r0, int r1, int r2, int r3) {
    x0 += x1; x1 = __funnelshift_l(x1, x1, r0); x1 ^= x0;
    x0 += x1; x1 = __funnelshift_l(x1, x1, r1); x1 ^= x0;
    x0 += x1; x1 = __funnelshift_l(x1, x1, r2); x1 ^= x0;
    x0 += x1; x1 = __funnelshift_l(x1, x1, r3); x1 ^= x0;
}
__device__ __forceinline__ void tf2x32_plain(unsigned k0, unsigned k1, unsigned k2,
                                             unsigned &x0, unsigned &x1) {
    x0 += k0; x1 += k1;
    tf_g4p(x0, x1, 13, 15, 26, 6);
    x0 += k1; x1 += k2 + 1u;
    tf_g4p(x0, x1, 17, 29, 16, 24);
    x0 += k2; x1 += k0 + 2u;
    tf_g4p(x0, x1, 13, 15, 26, 6);
    x0 += k0; x1 += k1 + 3u;
    tf_g4p(x0, x1, 17, 29, 16, 24);
    x0 += k1; x1 += k2 + 4u;
    tf_g4p(x0, x1, 13, 15, 26, 6);
    x0 += k2; x1 += k0 + 5u;
}

__global__ void k_init(const int* __restrict__ seedp) {
    int t = threadIdx.x;
    unsigned s = (unsigned)seedp[0];
    if (t < TT) {
        unsigned k0 = 0u, k1 = s;
        unsigned k2 = k0 ^ k1 ^ 0x1BD11BDAu;
        unsigned x0 = 0u, x1 = (unsigned)t;
        tf2x32_plain(k0, k1, k2, x0, x1);
        unsigned K0 = x0, K1 = x1;
        unsigned K2 = K0 ^ K1 ^ 0x1BD11BDAu;
        g_keyc[2 * t + 0] = make_uint4(K0, K1, K2, K2 + 1u);
        g_keyc[2 * t + 1] = make_uint4(K0 + 2u, K1 + 3u, K2 + 4u, K0 + 5u);
    }
    for (int q = t; q < NNEUR * 4; q += blockDim.x) g_potOcc[q] = 0u;
    if (t == 0) g_one = 1u;
}

// Hot kernel: fused threshold + 100 threefry blocks per element (validated R2).
__global__ void __launch_bounds__(256) k_rng(const float* __restrict__ x,
                                             const float* __restrict__ centers,
                                             const float* __restrict__ widths,
                                             const float* __restrict__ adapt) {
    __shared__ uint4 sk[TT * 2];
    int tid = threadIdx.x;
    if (tid < TT * 2) sk[tid] = g_keyc[tid];
    __syncthreads();

    unsigned i = blockIdx.x * 256u + tid;
    unsigned one = g_one;

    float xv = x[blockIdx.x];
    float c = centers[tid];
    float w = widths[tid];
    float d = xv - c;
    float num = -(d * d);
    float den = (2.0f * w) * w;
    float resp = expf(num / den);
    resp = resp * adapt[tid];
    float p = resp * 0.1f;
    unsigned T = (unsigned)ceilf(p * 8388608.0f);
    unsigned Tsh = T << 9;   // (bits>>9) < T  <=>  bits < (T<<9), T < 2^20

    unsigned mask[4];
#pragma unroll
    for (int w4 = 0; w4 < 4; w4++) {
        unsigned mw = 0u;
        const int nb = (w4 < 3) ? 32 : 4;
#pragma unroll 4
        for (int b = 0; b < nb; b++) {
            int t = w4 * 32 + b;
            uint4 c1 = sk[2 * t + 0];
            uint4 c2 = sk[2 * t + 1];
            unsigned x0 = c1.x;
            unsigned x1 = addf(i, c1.y, one);
            TF_ROUND(x0, x1, 13) TF_ROUND(x0, x1, 15)
            TF_ROUND(x0, x1, 26) TF_ROUND(x0, x1, 6)
            x0 = addf(x0, c1.y, one); x1 = addf(x1, c1.w, one);
            TF_ROUND(x0, x1, 17) TF_ROUND(x0, x1, 29)
            TF_ROUND(x0, x1, 16) TF_ROUND(x0, x1, 24)
            x0 = addf(x0, c1.z, one); x1 = addf(x1, c2.x, one);
            TF_ROUND(x0, x1, 13) TF_ROUND(x0, x1, 15)
            TF_ROUND(x0, x1, 26) TF_ROUND(x0, x1, 6)
            x0 = addf(x0, c1.x, one); x1 = addf(x1, c2.y, one);
            TF_ROUND(x0, x1, 17) TF_ROUND(x0, x1, 29)
            TF_ROUND(x0, x1, 16) TF_ROUND(x0, x1, 24)
            x0 = addf(x0, c1.y, one); x1 = addf(x1, c2.z, one);
            TF_ROUND(x0, x1, 13) TF_ROUND(x0, x1, 15)
            TF_ROUND(x0, x1, 26) TF_ROUND(x0, x1, 6)
            x0 = addf(x0, c1.z, one); x1 = addf(x1, c2.w, one);
            unsigned bits = x0 ^ x1;
            mw |= (bits < Tsh) ? (1u << b) : 0u;
        }
        mask[w4] = mw;
    }

    g_sbits[i] = make_uint4(mask[0], mask[1], mask[2], mask[3]);

    if (mask[0]) atomicOr(&g_potOcc[tid * 4 + 0], mask[0]);
    if (mask[1]) atomicOr(&g_potOcc[tid * 4 + 1], mask[1]);
    if (mask[2]) atomicOr(&g_potOcc[tid * 4 + 2], mask[2]);
    if (mask[3]) atomicOr(&g_potOcc[tid * 4 + 3], mask[3]);
}

__global__ void k_scan(const float* __restrict__ refr) {
    int n = threadIdx.x;
    unsigned p0 = g_potOcc[n * 4 + 0], p1 = g_potOcc[n * 4 + 1];
    unsigned p2 = g_potOcc[n * 4 + 2], p3 = g_potOcc[n * 4 + 3];
    float ref = refr[n];
    unsigned g0 = 0u, g1 = 0u, g2 = 0u, g3 = 0u;
#pragma unroll
    for (int t = 0; t < TT; t++) {
        unsigned pw = (t < 32) ? p0 : ((t < 64) ? p1 : ((t < 96) ? p2 : p3));
        bool active = (ref == 0.0f);
        unsigned bit = (pw >> (t & 31)) & 1u;
        unsigned occ = active ? bit : 0u;
        unsigned gbit = active ? 1u : 0u;
        if (t < 32)      g0 |= gbit << t;
        else if (t < 64) g1 |= gbit << (t - 32);
        else if (t < 96) g2 |= gbit << (t - 64);
        else             g3 |= gbit << (t - 96);
        ref = fmaxf(ref - 1.0f, 0.0f) + 2.0f * (float)occ;
    }
    g_gate[n * 4 + 0] = g0; g_gate[n * 4 + 1] = g1;
    g_gate[n * 4 + 2] = g2; g_gate[n * 4 + 3] = g3;
}

// k_out: element pairs (200 bits = 25 bytes) -> byte LUT -> coalesced stores.
// Grid 1024 x 800 threads. Per block: 256 pairs (512 elements).
// Thread j: pl=j/25, r=j%25 (fixed). 8 iterations of 32 pairs; lane j writes
// floats [8j, 8j+8) of each 6400-float chunk -> warp writes contiguous 1KB.
__global__ void __launch_bounds__(800) k_out(float* __restrict__ out) {
    __shared__ float lutf[256 * 8];     // byte value -> 8 floats (0/1 per bit)
    __shared__ unsigned sb[256 * 8];    // per pair: 25-byte packed bits (+pad)

    int j = threadIdx.x;

    // Build LUT (256 threads)
    if (j < 256) {
#pragma unroll
        for (int k = 0; k < 8; k++)
            lutf[j * 8 + k] = (float)((j >> k) & 1u);
    }

    // Stage: gate + pack element pairs into byte stream
    if (j < 256) {
        unsigned gp = blockIdx.x * 256u + j;       // global pair index
        unsigned e0 = 2u * gp;
        uint4 s0 = g_sbits[e0];
        uint4 s1 = g_sbits[e0 + 1u];
        int n0 = (int)((2u * (unsigned)j) & 255u); // neuron of e0 (e0 even)
        int n1 = n0 + 1;
        unsigned a0 = s0.x & g_gate[n0 * 4 + 0];
        unsigned a1 = s0.y & g_gate[n0 * 4 + 1];
        unsigned a2 = s0.z & g_gate[n0 * 4 + 2];
        unsigned a3 = s0.w & g_gate[n0 * 4 + 3];
        unsigned b0 = s1.x & g_gate[n1 * 4 + 0];
        unsigned b1 = s1.y & g_gate[n1 * 4 + 1];
        unsigned b2 = s1.z & g_gate[n1 * 4 + 2];
        unsigned b3 = s1.w & g_gate[n1 * 4 + 3];
        // concat 200 bits: e0 bits 0..99 then e1 bits 0..99 (LSB-first)
        unsigned u3 = (a3 & 0xFu) | (b0 << 4);
        unsigned u4 = (b0 >> 28) | (b1 << 4);
        unsigned u5 = (b1 >> 28) | (b2 << 4);
        unsigned u6 = (b2 >> 28) | ((b3 & 0xFu) << 4);   // FIXED (was << 28)
        sb[j * 8 + 0] = a0; sb[j * 8 + 1] = a1;
        sb[j * 8 + 2] = a2; sb[j * 8 + 3] = u3;
        sb[j * 8 + 4] = u4; sb[j * 8 + 5] = u5;
        sb[j * 8 + 6] = u6; sb[j * 8 + 7] = 0u;
    }
    __syncthreads();

    int pl = j / 25;          // pair-in-iteration (0..31)
    int r  = j % 25;          // byte-in-pair (0..24)
    const unsigned char* sbb = (const unsigned char*)sb;

    // lane j writes float4s at chunk_base + 2j, chunk stride 1600 float4
    float4* optr = reinterpret_cast<float4*>(out) +
                   (size_t)blockIdx.x * 12800 + 2 * j;
#pragma unroll
    for (int it = 0; it < 8; it++) {
        int p = it * 32 + pl;
        unsigned byte = sbb[p * 32 + r];
        const float4* lv = reinterpret_cast<const float4*>(lutf) + byte * 2;
        float4 v0 = lv[0];
        float4 v1 = lv[1];
        optr[it * 1600 + 0] = v0;
        optr[it * 1600 + 1] = v1;
    }
}

extern "C" void kernel_launch(void* const* d_in, const int* in_sizes, int n_in,
                              void* d_out, int out_size) {
    (void)in_sizes; (void)n_in; (void)out_size;
    const float* x       = (const float*)d_in[0];
    const float* centers = (const float*)d_in[1];
    const float* widths  = (const float*)d_in[2];
    const float* adapt   = (const float*)d_in[3];
    const float* refr    = (const float*)d_in[4];
    const int*   seed    = (const int*)d_in[5];
    float* out = (float*)d_out;

    k_init<<<1, 256>>>(seed);
    k_rng <<<NBLK, 256>>>(x, centers, widths, adapt);
    k_scan<<<1, NNEUR>>>(refr);
    k_out <<<1024, 800>>>(out);
}

// round 6
// speedup vs baseline: 1.6708x; 1.1199x over previous
#include <cuda_runtime.h>
#include <cuda_bf16.h>

// TactileSpikeEncoder: bit-exact JAX threefry2x32 (partitionable) spike encoder.
// R5: k_rng pipe-balance — convert 4 of 20 rotations to mulhi/mullo (fma pipe)
//     with OR+XOR merged into one LOP3 (alu 43->39, fma 31->39 per block);
//     2 elements per thread (shared key LDS, 2 indep chains, halved atomics).
//     k_out: LUT split into two 16B-stride tables to spread smem banks.

#define TT      100
#define NNEUR   256
#define TOTAL   524288   // 32*64*256
#define HALF    262144

__device__ uint4    g_keyc[TT * 2];         // per t: {k0,k1,k2,k2+1},{k0+2,k1+3,k2+4,k0+5}
__device__ uint4    g_sbits[TOTAL];         // 100-bit candidate mask per element (8 MB)
__device__ unsigned g_potOcc[NNEUR * 4];
__device__ unsigned g_gate[NNEUR * 4];
__device__ unsigned g_one;

__device__ __forceinline__ unsigned addf(unsigned a, unsigned b, unsigned one) {
    unsigned d;
    asm("mad.lo.u32 %0, %1, %2, %3;" : "=r"(d) : "r"(a), "r"(one), "r"(b));
    return d;
}
__device__ __forceinline__ unsigned mullo(unsigned a, unsigned b) {
    unsigned d;
    asm("mul.lo.u32 %0, %1, %2;" : "=r"(d) : "r"(a), "r"(b));
    return d;
}
__device__ __forceinline__ unsigned mulhi_(unsigned a, unsigned b) {
    unsigned d;
    asm("mul.hi.u32 %0, %1, %2;" : "=r"(d) : "r"(a), "r"(b));
    return d;
}

// Type-A round: add(fma) + SHF(alu) + XOR(alu)
#define TF_ROUND(x0, x1, R)                    \
    x0 = addf(x0, x1, one);                    \
    x1 = __funnelshift_l(x1, x1, R);           \
    x1 ^= x0;

// Type-B round: add(fma) + mulhi(fma) + mullo(fma) + merged (hi|lo)^x0 LOP3(alu)
#define TF_ROUND_M(x0, x1, P) {                \
    unsigned hi_ = mulhi_(x1, P);              \
    unsigned lo_ = mullo(x1, P);               \
    x0 = addf(x0, x1, one);                    \
    x1 = (hi_ | lo_) ^ x0; }

// One full threefry2x32 for counter (0, i) with precomputed const table c1/c2.
// Groups 1,3,5 use rotations {13,15,26,6} with R=26 converted to type-B;
// group 2 uses {17,29,16,24} with R=16 converted. (4 conversions -> pipes balanced.)
#define TF_BLOCK(x0, x1, c1, c2, p26, p16)                         \
    x0 = c1.x;                                                     \
    x1 = addf(x1in, c1.y, one);                                    \
    TF_ROUND(x0, x1, 13) TF_ROUND(x0, x1, 15)                      \
    TF_ROUND_M(x0, x1, p26) TF_ROUND(x0, x1, 6)                    \
    x0 = addf(x0, c1.y, one); x1 = addf(x1, c1.w, one);            \
    TF_ROUND(x0, x1, 17) TF_ROUND(x0, x1, 29)                      \
    TF_ROUND_M(x0, x1, p16) TF_ROUND(x0, x1, 24)                   \
    x0 = addf(x0, c1.z, one); x1 = addf(x1, c2.x, one);            \
    TF_ROUND(x0, x1, 13) TF_ROUND(x0, x1, 15)                      \
    TF_ROUND_M(x0, x1, p26) TF_ROUND(x0, x1, 6)                    \
    x0 = addf(x0, c1.x, one); x1 = addf(x1, c2.y, one);            \
    TF_ROUND(x0, x1, 17) TF_ROUND(x0, x1, 29)                      \
    TF_ROUND(x0, x1, 16) TF_ROUND(x0, x1, 24)                      \
    x0 = addf(x0, c1.y, one); x1 = addf(x1, c2.z, one);            \
    TF_ROUND(x0, x1, 13) TF_ROUND(x0, x1, 15)                      \
    TF_ROUND_M(x0, x1, p26) TF_ROUND(x0, x1, 6)                    \
    x0 = addf(x0, c1.z, one); x1 = addf(x1, c2.w, one);

__device__ __forceinline__ void tf_g4p(unsigned &x0, unsigned &x1,
                                       int r0, int r1, int r2, int r3) {
    x0 += x1; x1 = __funnelshift_l(x1, x1, r0); x1 ^= x0;
    x0 += x1; x1 = __funnelshift_l(x1, x1, r1); x1 ^= x0;
    x0 += x1; x1 = __funnelshift_l(x1, x1, r2); x1 ^= x0;
    x0 += x1; x1 = __funnelshift_l(x1, x1, r3); x1 ^= x0;
}
__device__ __forceinline__ void tf2x32_plain(unsigned k0, unsigned k1, unsigned k2,
                                             unsigned &x0, unsigned &x1) {
    x0 += k0; x1 += k1;
    tf_g4p(x0, x1, 13, 15, 26, 6);
    x0 += k1; x1 += k2 + 1u;
    tf_g4p(x0, x1, 17, 29, 16, 24);
    x0 += k2; x1 += k0 + 2u;
    tf_g4p(x0, x1, 13, 15, 26, 6);
    x0 += k0; x1 += k1 + 3u;
    tf_g4p(x0, x1, 17, 29, 16, 24);
    x0 += k1; x1 += k2 + 4u;
    tf_g4p(x0, x1, 13, 15, 26, 6);
    x0 += k2; x1 += k0 + 5u;
}

__global__ void k_init(const int* __restrict__ seedp) {
    int t = threadIdx.x;
    unsigned s = (unsigned)seedp[0];
    if (t < TT) {
        unsigned k0 = 0u, k1 = s;
        unsigned k2 = k0 ^ k1 ^ 0x1BD11BDAu;
        unsigned x0 = 0u, x1 = (unsigned)t;
        tf2x32_plain(k0, k1, k2, x0, x1);
        unsigned K0 = x0, K1 = x1;
        unsigned K2 = K0 ^ K1 ^ 0x1BD11BDAu;
        g_keyc[2 * t + 0] = make_uint4(K0, K1, K2, K2 + 1u);
        g_keyc[2 * t + 1] = make_uint4(K0 + 2u, K1 + 3u, K2 + 4u, K0 + 5u);
    }
    for (int q = t; q < NNEUR * 4; q += blockDim.x) g_potOcc[q] = 0u;
    if (t == 0) g_one = 1u;
}

// Hot kernel: fused threshold + RNG. 2 elements per thread: i and i+HALF
// (same neuron tid -> shared key LDS, merged atomics, 2 independent chains).
__global__ void __launch_bounds__(256) k_rng(const float* __restrict__ x,
                                             const float* __restrict__ centers,
                                             const float* __restrict__ widths,
                                             const float* __restrict__ adapt) {
    __shared__ uint4 sk[TT * 2];
    int tid = threadIdx.x;
    if (tid < TT * 2) sk[tid] = g_keyc[tid];
    __syncthreads();

    unsigned iA = blockIdx.x * 256u + tid;
    unsigned iB = iA + HALF;
    unsigned one = g_one;
    unsigned p26 = one << 26;
    unsigned p16 = one << 16;

    float c = centers[tid];
    float w = widths[tid];
    float ad = adapt[tid];
    float den = (2.0f * w) * w;

    float xvA = x[blockIdx.x];
    float dA = xvA - c;
    float pA = expf(-(dA * dA) / den) * ad * 0.1f;
    unsigned TshA = ((unsigned)ceilf(pA * 8388608.0f)) << 9;

    float xvB = x[blockIdx.x + 1024];
    float dB = xvB - c;
    float pB = expf(-(dB * dB) / den) * ad * 0.1f;
    unsigned TshB = ((unsigned)ceilf(pB * 8388608.0f)) << 9;

    unsigned maskA[4], maskB[4];
#pragma unroll
    for (int w4 = 0; w4 < 4; w4++) {
        unsigned mA = 0u, mB = 0u;
        const int nb = (w4 < 3) ? 32 : 4;
#pragma unroll 2
        for (int b = 0; b < nb; b++) {
            int t = w4 * 32 + b;
            uint4 c1 = sk[2 * t + 0];
            uint4 c2 = sk[2 * t + 1];
            unsigned x0a, x1a, x0b, x1b;
            { unsigned x1in = iA; TF_BLOCK(x0a, x1a, c1, c2, p26, p16) }
            { unsigned x1in = iB; TF_BLOCK(x0b, x1b, c1, c2, p26, p16) }
            unsigned bitsA = x0a ^ x1a;
            unsigned bitsB = x0b ^ x1b;
            if (bitsA < TshA) mA |= (1u << b);
            if (bitsB < TshB) mB |= (1u << b);
        }
        maskA[w4] = mA;
        maskB[w4] = mB;
    }

    g_sbits[iA] = make_uint4(maskA[0], maskA[1], maskA[2], maskA[3]);
    g_sbits[iB] = make_uint4(maskB[0], maskB[1], maskB[2], maskB[3]);

#pragma unroll
    for (int q = 0; q < 4; q++) {
        unsigned m = maskA[q] | maskB[q];
        if (m) atomicOr(&g_potOcc[tid * 4 + q], m);
    }
}

__global__ void k_scan(const float* __restrict__ refr) {
    int n = threadIdx.x;
    unsigned p0 = g_potOcc[n * 4 + 0], p1 = g_potOcc[n * 4 + 1];
    unsigned p2 = g_potOcc[n * 4 + 2], p3 = g_potOcc[n * 4 + 3];
    float ref = refr[n];
    unsigned g0 = 0u, g1 = 0u, g2 = 0u, g3 = 0u;
#pragma unroll
    for (int t = 0; t < TT; t++) {
        unsigned pw = (t < 32) ? p0 : ((t < 64) ? p1 : ((t < 96) ? p2 : p3));
        bool active = (ref == 0.0f);
        unsigned bit = (pw >> (t & 31)) & 1u;
        unsigned occ = active ? bit : 0u;
        unsigned gbit = active ? 1u : 0u;
        if (t < 32)      g0 |= gbit << t;
        else if (t < 64) g1 |= gbit << (t - 32);
        else if (t < 96) g2 |= gbit << (t - 64);
        else             g3 |= gbit << (t - 96);
        ref = fmaxf(ref - 1.0f, 0.0f) + 2.0f * (float)occ;
    }
    g_gate[n * 4 + 0] = g0; g_gate[n * 4 + 1] = g1;
    g_gate[n * 4 + 2] = g2; g_gate[n * 4 + 3] = g3;
}

// k_out: element pairs (200 bits = 25 bytes) -> two 16B-stride byte LUTs ->
// coalesced 1KB/warp stores. Grid 1024 x 800 threads, 256 pairs/block.
__global__ void __launch_bounds__(800) k_out(float* __restrict__ out) {
    __shared__ float4 lutA[256];        // byte -> floats of bits 0..3
    __shared__ float4 lutB[256];        // byte -> floats of bits 4..7
    __shared__ unsigned sb[256 * 8];    // per pair: 25-byte packed bits (+pad)

    int j = threadIdx.x;

    if (j < 256) {
        lutA[j] = make_float4((float)(j & 1), (float)((j >> 1) & 1),
                              (float)((j >> 2) & 1), (float)((j >> 3) & 1));
        lutB[j] = make_float4((float)((j >> 4) & 1), (float)((j >> 5) & 1),
                              (float)((j >> 6) & 1), (float)((j >> 7) & 1));
    }

    if (j < 256) {
        unsigned gp = blockIdx.x * 256u + j;       // global pair index
        unsigned e0 = 2u * gp;
        uint4 s0 = g_sbits[e0];
        uint4 s1 = g_sbits[e0 + 1u];
        int n0 = (int)((2u * (unsigned)j) & 255u);
        int n1 = n0 + 1;
        unsigned a0 = s0.x & g_gate[n0 * 4 + 0];
        unsigned a1 = s0.y & g_gate[n0 * 4 + 1];
        unsigned a2 = s0.z & g_gate[n0 * 4 + 2];
        unsigned a3 = s0.w & g_gate[n0 * 4 + 3];
        unsigned b0 = s1.x & g_gate[n1 * 4 + 0];
        unsigned b1 = s1.y & g_gate[n1 * 4 + 1];
        unsigned b2 = s1.z & g_gate[n1 * 4 + 2];
        unsigned b3 = s1.w & g_gate[n1 * 4 + 3];
        unsigned u3 = (a3 & 0xFu) | (b0 << 4);
        unsigned u4 = (b0 >> 28) | (b1 << 4);
        unsigned u5 = (b1 >> 28) | (b2 << 4);
        unsigned u6 = (b2 >> 28) | ((b3 & 0xFu) << 4);
        sb[j * 8 + 0] = a0; sb[j * 8 + 1] = a1;
        sb[j * 8 + 2] = a2; sb[j * 8 + 3] = u3;
        sb[j * 8 + 4] = u4; sb[j * 8 + 5] = u5;
        sb[j * 8 + 6] = u6; sb[j * 8 + 7] = 0u;
    }
    __syncthreads();

    int pl = j / 25;          // pair-in-iteration (0..31)
    int r  = j % 25;          // byte-in-pair (0..24)
    const unsigned char* sbb = (const unsigned char*)sb;

    float4* optr = reinterpret_cast<float4*>(out) +
                   (size_t)blockIdx.x * 12800 + 2 * j;
#pragma unroll
    for (int it = 0; it < 8; it++) {
        int p = it * 32 + pl;
        unsigned byte = sbb[p * 32 + r];
        float4 v0 = lutA[byte];
        float4 v1 = lutB[byte];
        optr[it * 1600 + 0] = v0;
        optr[it * 1600 + 1] = v1;
    }
}

extern "C" void kernel_launch(void* const* d_in, const int* in_sizes, int n_in,
                              void* d_out, int out_size) {
    (void)in_sizes; (void)n_in; (void)out_size;
    const float* x       = (const float*)d_in[0];
    const float* centers = (const float*)d_in[1];
    const float* widths  = (const float*)d_in[2];
    const float* adapt   = (const float*)d_in[3];
    const float* refr    = (const float*)d_in[4];
    const int*   seed    = (const int*)d_in[5];
    float* out = (float*)d_out;

    k_init<<<1, 256>>>(seed);
    k_rng <<<1024, 256>>>(x, centers, widths, adapt);
    k_scan<<<1, NNEUR>>>(refr);
    k_out <<<1024, 800>>>(out);
}

// round 7
// speedup vs baseline: 1.9526x; 1.1686x over previous
#include <cuda_runtime.h>
#include <cuda_bf16.h>

// TactileSpikeEncoder: bit-exact JAX threefry2x32 (partitionable) spike encoder.
// R6: output is ~99% zeros. k_rng (compute-bound, idle DRAM) now also streams
//     the 210MB zero-fill (hidden under compute); dense k_out (57us) replaced
//     by k_sparse writing only the ~1M spike 1.0f values (~12us).
// Pipeline: k_init -> k_rng (thresh+RNG+potOcc+zero-fill) -> k_scan -> k_sparse

#define TT      100
#define NNEUR   256
#define TOTAL   524288   // 32*64*256
#define HALF    262144

__device__ uint4    g_keyc[TT * 2];         // per t: {k0,k1,k2,k2+1},{k0+2,k1+3,k2+4,k0+5}
__device__ uint4    g_sbits[TOTAL];         // 100-bit candidate mask per element (8 MB)
__device__ unsigned g_potOcc[NNEUR * 4];
__device__ unsigned g_gate[NNEUR * 4];      // transposed: g_gate[q*NNEUR + n]
__device__ unsigned g_one;

__device__ __forceinline__ unsigned addf(unsigned a, unsigned b, unsigned one) {
    unsigned d;
    asm("mad.lo.u32 %0, %1, %2, %3;" : "=r"(d) : "r"(a), "r"(one), "r"(b));
    return d;
}
__device__ __forceinline__ unsigned mullo(unsigned a, unsigned b) {
    unsigned d;
    asm("mul.lo.u32 %0, %1, %2;" : "=r"(d) : "r"(a), "r"(b));
    return d;
}
__device__ __forceinline__ unsigned mulhi_(unsigned a, unsigned b) {
    unsigned d;
    asm("mul.hi.u32 %0, %1, %2;" : "=r"(d) : "r"(a), "r"(b));
    return d;
}

// Type-A round: add(fma) + SHF(alu) + XOR(alu)
#define TF_ROUND(x0, x1, R)                    \
    x0 = addf(x0, x1, one);                    \
    x1 = __funnelshift_l(x1, x1, R);           \
    x1 ^= x0;

// Type-B round: add(fma) + mulhi(fma) + mullo(fma) + merged (hi|lo)^x0 LOP3(alu)
#define TF_ROUND_M(x0, x1, P) {                \
    unsigned hi_ = mulhi_(x1, P);              \
    unsigned lo_ = mullo(x1, P);               \
    x0 = addf(x0, x1, one);                    \
    x1 = (hi_ | lo_) ^ x0; }

#define TF_BLOCK(x0, x1, c1, c2, p26, p16)                         \
    x0 = c1.x;                                                     \
    x1 = addf(x1in, c1.y, one);                                    \
    TF_ROUND(x0, x1, 13) TF_ROUND(x0, x1, 15)                      \
    TF_ROUND_M(x0, x1, p26) TF_ROUND(x0, x1, 6)                    \
    x0 = addf(x0, c1.y, one); x1 = addf(x1, c1.w, one);            \
    TF_ROUND(x0, x1, 17) TF_ROUND(x0, x1, 29)                      \
    TF_ROUND_M(x0, x1, p16) TF_ROUND(x0, x1, 24)                   \
    x0 = addf(x0, c1.z, one); x1 = addf(x1, c2.x, one);            \
    TF_ROUND(x0, x1, 13) TF_ROUND(x0, x1, 15)                      \
    TF_ROUND_M(x0, x1, p26) TF_ROUND(x0, x1, 6)                    \
    x0 = addf(x0, c1.x, one); x1 = addf(x1, c2.y, one);            \
    TF_ROUND(x0, x1, 17) TF_ROUND(x0, x1, 29)                      \
    TF_ROUND(x0, x1, 16) TF_ROUND(x0, x1, 24)                      \
    x0 = addf(x0, c1.y, one); x1 = addf(x1, c2.z, one);            \
    TF_ROUND(x0, x1, 13) TF_ROUND(x0, x1, 15)                      \
    TF_ROUND_M(x0, x1, p26) TF_ROUND(x0, x1, 6)                    \
    x0 = addf(x0, c1.z, one); x1 = addf(x1, c2.w, one);

__device__ __forceinline__ void tf_g4p(unsigned &x0, unsigned &x1,
                                       int r0, int r1, int r2, int r3) {
    x0 += x1; x1 = __funnelshift_l(x1, x1, r0); x1 ^= x0;
    x0 += x1; x1 = __funnelshift_l(x1, x1, r1); x1 ^= x0;
    x0 += x1; x1 = __funnelshift_l(x1, x1, r2); x1 ^= x0;
    x0 += x1; x1 = __funnelshift_l(x1, x1, r3); x1 ^= x0;
}
__device__ __forceinline__ void tf2x32_plain(unsigned k0, unsigned k1, unsigned k2,
                                             unsigned &x0, unsigned &x1) {
    x0 += k0; x1 += k1;
    tf_g4p(x0, x1, 13, 15, 26, 6);
    x0 += k1; x1 += k2 + 1u;
    tf_g4p(x0, x1, 17, 29, 16, 24);
    x0 += k2; x1 += k0 + 2u;
    tf_g4p(x0, x1, 13, 15, 26, 6);
    x0 += k0; x1 += k1 + 3u;
    tf_g4p(x0, x1, 17, 29, 16, 24);
    x0 += k1; x1 += k2 + 4u;
    tf_g4p(x0, x1, 13, 15, 26, 6);
    x0 += k2; x1 += k0 + 5u;
}

__global__ void k_init(const int* __restrict__ seedp) {
    int t = threadIdx.x;
    unsigned s = (unsigned)seedp[0];
    if (t < TT) {
        unsigned k0 = 0u, k1 = s;
        unsigned k2 = k0 ^ k1 ^ 0x1BD11BDAu;
        unsigned x0 = 0u, x1 = (unsigned)t;
        tf2x32_plain(k0, k1, k2, x0, x1);
        unsigned K0 = x0, K1 = x1;
        unsigned K2 = K0 ^ K1 ^ 0x1BD11BDAu;
        g_keyc[2 * t + 0] = make_uint4(K0, K1, K2, K2 + 1u);
        g_keyc[2 * t + 1] = make_uint4(K0 + 2u, K1 + 3u, K2 + 4u, K0 + 5u);
    }
    for (int q = t; q < NNEUR * 4; q += blockDim.x) g_potOcc[q] = 0u;
    if (t == 0) g_one = 1u;
}

// Hot kernel: fused threshold + RNG (2 elements/thread: i, i+HALF) + zero-fill
// of this block's two 100KB output regions (DRAM hidden under compute).
__global__ void __launch_bounds__(256) k_rng(const float* __restrict__ x,
                                             const float* __restrict__ centers,
                                             const float* __restrict__ widths,
                                             const float* __restrict__ adapt,
                                             float* __restrict__ out) {
    __shared__ uint4 sk[TT * 2];
    int tid = threadIdx.x;
    if (tid < TT * 2) sk[tid] = g_keyc[tid];
    __syncthreads();

    // Zero-fill: block covers elements [blk*256, blk*256+256) and +HALF.
    // float4 regions: [blk*6400, +6400) and [blk*6400 + HALF*25, +6400).
    {
        float4 z = make_float4(0.f, 0.f, 0.f, 0.f);
        float4* oA = reinterpret_cast<float4*>(out) + (size_t)blockIdx.x * 6400 + tid;
        float4* oB = oA + (size_t)HALF * 25;
#pragma unroll
        for (int k = 0; k < 25; k++) {
            oA[k * 256] = z;
            oB[k * 256] = z;
        }
    }

    unsigned iA = blockIdx.x * 256u + tid;
    unsigned iB = iA + HALF;
    unsigned one = g_one;
    unsigned p26 = one << 26;
    unsigned p16 = one << 16;

    float c = centers[tid];
    float w = widths[tid];
    float ad = adapt[tid];
    float den = (2.0f * w) * w;

    float xvA = x[blockIdx.x];
    float dA = xvA - c;
    float pA = expf(-(dA * dA) / den) * ad * 0.1f;
    unsigned TshA = ((unsigned)ceilf(pA * 8388608.0f)) << 9;

    float xvB = x[blockIdx.x + 1024];
    float dB = xvB - c;
    float pB = expf(-(dB * dB) / den) * ad * 0.1f;
    unsigned TshB = ((unsigned)ceilf(pB * 8388608.0f)) << 9;

    unsigned maskA[4], maskB[4];
#pragma unroll
    for (int w4 = 0; w4 < 4; w4++) {
        unsigned mA = 0u, mB = 0u;
        const int nb = (w4 < 3) ? 32 : 4;
#pragma unroll 2
        for (int b = 0; b < nb; b++) {
            int t = w4 * 32 + b;
            uint4 c1 = sk[2 * t + 0];
            uint4 c2 = sk[2 * t + 1];
            unsigned x0a, x1a, x0b, x1b;
            { unsigned x1in = iA; TF_BLOCK(x0a, x1a, c1, c2, p26, p16) }
            { unsigned x1in = iB; TF_BLOCK(x0b, x1b, c1, c2, p26, p16) }
            unsigned bitsA = x0a ^ x1a;
            unsigned bitsB = x0b ^ x1b;
            if (bitsA < TshA) mA |= (1u << b);
            if (bitsB < TshB) mB |= (1u << b);
        }
        maskA[w4] = mA;
        maskB[w4] = mB;
    }

    g_sbits[iA] = make_uint4(maskA[0], maskA[1], maskA[2], maskA[3]);
    g_sbits[iB] = make_uint4(maskB[0], maskB[1], maskB[2], maskB[3]);

#pragma unroll
    for (int q = 0; q < 4; q++) {
        unsigned m = maskA[q] | maskB[q];
        if (m) atomicOr(&g_potOcc[tid * 4 + q], m);
    }
}

// Refractory recurrence per neuron; gate stored TRANSPOSED (g_gate[q*N+n]).
__global__ void k_scan(const float* __restrict__ refr) {
    int n = threadIdx.x;
    unsigned p0 = g_potOcc[n * 4 + 0], p1 = g_potOcc[n * 4 + 1];
    unsigned p2 = g_potOcc[n * 4 + 2], p3 = g_potOcc[n * 4 + 3];
    float ref = refr[n];
    unsigned g0 = 0u, g1 = 0u, g2 = 0u, g3 = 0u;
#pragma unroll
    for (int t = 0; t < TT; t++) {
        unsigned pw = (t < 32) ? p0 : ((t < 64) ? p1 : ((t < 96) ? p2 : p3));
        bool active = (ref == 0.0f);
        unsigned bit = (pw >> (t & 31)) & 1u;
        unsigned occ = active ? bit : 0u;
        unsigned gbit = active ? 1u : 0u;
        if (t < 32)      g0 |= gbit << t;
        else if (t < 64) g1 |= gbit << (t - 32);
        else if (t < 96) g2 |= gbit << (t - 64);
        else             g3 |= gbit << (t - 96);
        ref = fmaxf(ref - 1.0f, 0.0f) + 2.0f * (float)occ;
    }
    g_gate[0 * NNEUR + n] = g0; g_gate[1 * NNEUR + n] = g1;
    g_gate[2 * NNEUR + n] = g2; g_gate[3 * NNEUR + n] = g3;
}

// Sparse pass: write 1.0f only at gated spike positions (~1M scattered stores).
__global__ void __launch_bounds__(256) k_sparse(float* __restrict__ out) {
    __shared__ unsigned sg[NNEUR * 4];   // transposed gate: sg[q*256+n]
    int tid = threadIdx.x;
    for (int q = tid; q < NNEUR * 4; q += 256) sg[q] = g_gate[q];
    __syncthreads();

    unsigned i = blockIdx.x * 256u + tid;
    uint4 s = g_sbits[i];
    unsigned w0 = s.x & sg[0 * NNEUR + tid];
    unsigned w1 = s.y & sg[1 * NNEUR + tid];
    unsigned w2 = s.z & sg[2 * NNEUR + tid];
    unsigned w3 = s.w & sg[3 * NNEUR + tid];

    float* o = out + (size_t)i * TT;
    while (w0) { int b = __ffs(w0) - 1; w0 &= w0 - 1; o[b] = 1.0f; }
    while (w1) { int b = __ffs(w1) - 1; w1 &= w1 - 1; o[32 + b] = 1.0f; }
    while (w2) { int b = __ffs(w2) - 1; w2 &= w2 - 1; o[64 + b] = 1.0f; }
    while (w3) { int b = __ffs(w3) - 1; w3 &= w3 - 1; o[96 + b] = 1.0f; }
}

extern "C" void kernel_launch(void* const* d_in, const int* in_sizes, int n_in,
                              void* d_out, int out_size) {
    (void)in_sizes; (void)n_in; (void)out_size;
    const float* x       = (const float*)d_in[0];
    const float* centers = (const float*)d_in[1];
    const float* widths  = (const float*)d_in[2];
    const float* adapt   = (const float*)d_in[3];
    const float* refr    = (const float*)d_in[4];
    const int*   seed    = (const int*)d_in[5];
    float* out = (float*)d_out;

    k_init  <<<1, 256>>>(seed);
    k_rng   <<<1024, 256>>>(x, centers, widths, adapt, out);
    k_scan  <<<1, NNEUR>>>(refr);
    k_sparse<<<2048, 256>>>(out);
}

// round 8
// speedup vs baseline: 2.1095x; 1.0804x over previous
#include <cuda_runtime.h>
#include <cuda_bf16.h>

// TactileSpikeEncoder: bit-exact JAX threefry2x32 (partitionable) spike encoder.
// R7: zero-fill stores interleaved through the threefry loop (front-batched
//     STGs caused cross-CTA L1tex-queue spread, ~+20us). Warp-uniform skip
//     when the whole warp's thresholds are zero.
// Pipeline: k_init -> k_rng (thresh+RNG+potOcc+zero-fill) -> k_scan -> k_sparse

#define TT      100
#define NNEUR   256
#define TOTAL   524288   // 32*64*256
#define HALF    262144

__device__ uint4    g_keyc[TT * 2];         // per t: {k0,k1,k2,k2+1},{k0+2,k1+3,k2+4,k0+5}
__device__ uint4    g_sbits[TOTAL];         // 100-bit candidate mask per element (8 MB)
__device__ unsigned g_potOcc[NNEUR * 4];
__device__ unsigned g_gate[NNEUR * 4];      // transposed: g_gate[q*NNEUR + n]
__device__ unsigned g_one;

__device__ __forceinline__ unsigned addf(unsigned a, unsigned b, unsigned one) {
    unsigned d;
    asm("mad.lo.u32 %0, %1, %2, %3;" : "=r"(d) : "r"(a), "r"(one), "r"(b));
    return d;
}
__device__ __forceinline__ unsigned mullo(unsigned a, unsigned b) {
    unsigned d;
    asm("mul.lo.u32 %0, %1, %2;" : "=r"(d) : "r"(a), "r"(b));
    return d;
}
__device__ __forceinline__ unsigned mulhi_(unsigned a, unsigned b) {
    unsigned d;
    asm("mul.hi.u32 %0, %1, %2;" : "=r"(d) : "r"(a), "r"(b));
    return d;
}

// Type-A round: add(fma) + SHF(alu) + XOR(alu)
#define TF_ROUND(x0, x1, R)                    \
    x0 = addf(x0, x1, one);                    \
    x1 = __funnelshift_l(x1, x1, R);           \
    x1 ^= x0;

// Type-B round: add(fma) + mulhi(fma) + mullo(fma) + merged (hi|lo)^x0 LOP3(alu)
#define TF_ROUND_M(x0, x1, P) {                \
    unsigned hi_ = mulhi_(x1, P);              \
    unsigned lo_ = mullo(x1, P);               \
    x0 = addf(x0, x1, one);                    \
    x1 = (hi_ | lo_) ^ x0; }

#define TF_BLOCK(x0, x1, c1, c2, p26, p16)                         \
    x0 = c1.x;                                                     \
    x1 = addf(x1in, c1.y, one);                                    \
    TF_ROUND(x0, x1, 13) TF_ROUND(x0, x1, 15)                      \
    TF_ROUND_M(x0, x1, p26) TF_ROUND(x0, x1, 6)                    \
    x0 = addf(x0, c1.y, one); x1 = addf(x1, c1.w, one);            \
    TF_ROUND(x0, x1, 17) TF_ROUND(x0, x1, 29)                      \
    TF_ROUND_M(x0, x1, p16) TF_ROUND(x0, x1, 24)                   \
    x0 = addf(x0, c1.z, one); x1 = addf(x1, c2.x, one);            \
    TF_ROUND(x0, x1, 13) TF_ROUND(x0, x1, 15)                      \
    TF_ROUND_M(x0, x1, p26) TF_ROUND(x0, x1, 6)                    \
    x0 = addf(x0, c1.x, one); x1 = addf(x1, c2.y, one);            \
    TF_ROUND(x0, x1, 17) TF_ROUND(x0, x1, 29)                      \
    TF_ROUND(x0, x1, 16) TF_ROUND(x0, x1, 24)                      \
    x0 = addf(x0, c1.y, one); x1 = addf(x1, c2.z, one);            \
    TF_ROUND(x0, x1, 13) TF_ROUND(x0, x1, 15)                      \
    TF_ROUND_M(x0, x1, p26) TF_ROUND(x0, x1, 6)                    \
    x0 = addf(x0, c1.z, one); x1 = addf(x1, c2.w, one);

__device__ __forceinline__ void tf_g4p(unsigned &x0, unsigned &x1,
                                       int r0, int r1, int r2, int r3) {
    x0 += x1; x1 = __funnelshift_l(x1, x1, r0); x1 ^= x0;
    x0 += x1; x1 = __funnelshift_l(x1, x1, r1); x1 ^= x0;
    x0 += x1; x1 = __funnelshift_l(x1, x1, r2); x1 ^= x0;
    x0 += x1; x1 = __funnelshift_l(x1, x1, r3); x1 ^= x0;
}
__device__ __forceinline__ void tf2x32_plain(unsigned k0, unsigned k1, unsigned k2,
                                             unsigned &x0, unsigned &x1) {
    x0 += k0; x1 += k1;
    tf_g4p(x0, x1, 13, 15, 26, 6);
    x0 += k1; x1 += k2 + 1u;
    tf_g4p(x0, x1, 17, 29, 16, 24);
    x0 += k2; x1 += k0 + 2u;
    tf_g4p(x0, x1, 13, 15, 26, 6);
    x0 += k0; x1 += k1 + 3u;
    tf_g4p(x0, x1, 17, 29, 16, 24);
    x0 += k1; x1 += k2 + 4u;
    tf_g4p(x0, x1, 13, 15, 26, 6);
    x0 += k2; x1 += k0 + 5u;
}

__global__ void k_init(const int* __restrict__ seedp) {
    int t = threadIdx.x;
    unsigned s = (unsigned)seedp[0];
    if (t < TT) {
        unsigned k0 = 0u, k1 = s;
        unsigned k2 = k0 ^ k1 ^ 0x1BD11BDAu;
        unsigned x0 = 0u, x1 = (unsigned)t;
        tf2x32_plain(k0, k1, k2, x0, x1);
        unsigned K0 = x0, K1 = x1;
        unsigned K2 = K0 ^ K1 ^ 0x1BD11BDAu;
        g_keyc[2 * t + 0] = make_uint4(K0, K1, K2, K2 + 1u);
        g_keyc[2 * t + 1] = make_uint4(K0 + 2u, K1 + 3u, K2 + 4u, K0 + 5u);
    }
    for (int q = t; q < NNEUR * 4; q += blockDim.x) g_potOcc[q] = 0u;
    if (t == 0) g_one = 1u;
}

// Compute one 32-bit (or 4-bit) mask word for both elements.
__device__ __forceinline__ void tf_w4(int w4, int nb, unsigned iA, unsigned iB,
                                      unsigned TshA, unsigned TshB,
                                      const uint4* sk, unsigned one,
                                      unsigned p26, unsigned p16,
                                      unsigned &mAout, unsigned &mBout) {
    unsigned mA = 0u, mB = 0u;
#pragma unroll 2
    for (int b = 0; b < nb; b++) {
        int t = w4 * 32 + b;
        uint4 c1 = sk[2 * t + 0];
        uint4 c2 = sk[2 * t + 1];
        unsigned x0a, x1a, x0b, x1b;
        { unsigned x1in = iA; TF_BLOCK(x0a, x1a, c1, c2, p26, p16) }
        { unsigned x1in = iB; TF_BLOCK(x0b, x1b, c1, c2, p26, p16) }
        unsigned bitsA = x0a ^ x1a;
        unsigned bitsB = x0b ^ x1b;
        if (bitsA < TshA) mA |= (1u << b);
        if (bitsB < TshB) mB |= (1u << b);
    }
    mAout = mA; mBout = mB;
}

// Hot kernel: fused threshold + RNG (2 elements/thread) + interleaved zero-fill.
__global__ void __launch_bounds__(256) k_rng(const float* __restrict__ x,
                                             const float* __restrict__ centers,
                                             const float* __restrict__ widths,
                                             const float* __restrict__ adapt,
                                             float* __restrict__ out) {
    __shared__ uint4 sk[TT * 2];
    int tid = threadIdx.x;
    if (tid < TT * 2) sk[tid] = g_keyc[tid];
    __syncthreads();

    unsigned iA = blockIdx.x * 256u + tid;
    unsigned iB = iA + HALF;
    unsigned one = g_one;
    unsigned p26 = one << 26;
    unsigned p16 = one << 16;

    float c = centers[tid];
    float w = widths[tid];
    float ad = adapt[tid];
    float den = (2.0f * w) * w;

    float xvA = x[blockIdx.x];
    float dA = xvA - c;
    float pA = expf(-(dA * dA) / den) * ad * 0.1f;
    unsigned TshA = ((unsigned)ceilf(pA * 8388608.0f)) << 9;

    float xvB = x[blockIdx.x + 1024];
    float dB = xvB - c;
    float pB = expf(-(dB * dB) / den) * ad * 0.1f;
    unsigned TshB = ((unsigned)ceilf(pB * 8388608.0f)) << 9;

    const float4 z = make_float4(0.f, 0.f, 0.f, 0.f);
    float4* oA = reinterpret_cast<float4*>(out) + (size_t)blockIdx.x * 6400 + tid;
    float4* oB = oA + (size_t)HALF * 25;

#define ZCHUNK(K0_, K1_)                               \
    asm volatile("" ::: "memory");                     \
    _Pragma("unroll")                                  \
    for (int k = (K0_); k < (K1_); k++) {              \
        oA[k * 256] = z; oB[k * 256] = z;              \
    }                                                  \
    asm volatile("" ::: "memory");

    unsigned maskA[4], maskB[4];

    bool skip = __all_sync(0xFFFFFFFFu, (TshA | TshB) == 0u);
    if (!skip) {
        // Interleave zero-fill chunks with the 4 compute sections so the STGs
        // never front-batch (avoids cross-CTA L1tex-queue contention spread).
        ZCHUNK(0, 8)
        tf_w4(0, 32, iA, iB, TshA, TshB, sk, one, p26, p16, maskA[0], maskB[0]);
        ZCHUNK(8, 16)
        tf_w4(1, 32, iA, iB, TshA, TshB, sk, one, p26, p16, maskA[1], maskB[1]);
        ZCHUNK(16, 24)
        tf_w4(2, 32, iA, iB, TshA, TshB, sk, one, p26, p16, maskA[2], maskB[2]);
        ZCHUNK(24, 25)
        tf_w4(3, 4, iA, iB, TshA, TshB, sk, one, p26, p16, maskA[3], maskB[3]);
    } else {
#pragma unroll
        for (int k = 0; k < 25; k++) { oA[k * 256] = z; oB[k * 256] = z; }
#pragma unroll
        for (int q = 0; q < 4; q++) { maskA[q] = 0u; maskB[q] = 0u; }
    }
#undef ZCHUNK

    g_sbits[iA] = make_uint4(maskA[0], maskA[1], maskA[2], maskA[3]);
    g_sbits[iB] = make_uint4(maskB[0], maskB[1], maskB[2], maskB[3]);

#pragma unroll
    for (int q = 0; q < 4; q++) {
        unsigned m = maskA[q] | maskB[q];
        if (m) atomicOr(&g_potOcc[tid * 4 + q], m);
    }
}

// Refractory recurrence per neuron; gate stored TRANSPOSED (g_gate[q*N+n]).
__global__ void k_scan(const float* __restrict__ refr) {
    int n = threadIdx.x;
    unsigned p0 = g_potOcc[n * 4 + 0], p1 = g_potOcc[n * 4 + 1];
    unsigned p2 = g_potOcc[n * 4 + 2], p3 = g_potOcc[n * 4 + 3];
    float ref = refr[n];
    unsigned g0 = 0u, g1 = 0u, g2 = 0u, g3 = 0u;
#pragma unroll
    for (int t = 0; t < TT; t++) {
        unsigned pw = (t < 32) ? p0 : ((t < 64) ? p1 : ((t < 96) ? p2 : p3));
        bool active = (ref == 0.0f);
        unsigned bit = (pw >> (t & 31)) & 1u;
        unsigned occ = active ? bit : 0u;
        unsigned gbit = active ? 1u : 0u;
        if (t < 32)      g0 |= gbit << t;
        else if (t < 64) g1 |= gbit << (t - 32);
        else if (t < 96) g2 |= gbit << (t - 64);
        else             g3 |= gbit << (t - 96);
        ref = fmaxf(ref - 1.0f, 0.0f) + 2.0f * (float)occ;
    }
    g_gate[0 * NNEUR + n] = g0; g_gate[1 * NNEUR + n] = g1;
    g_gate[2 * NNEUR + n] = g2; g_gate[3 * NNEUR + n] = g3;
}

// Sparse pass: write 1.0f only at gated spike positions (~1M scattered stores).
__global__ void __launch_bounds__(256) k_sparse(float* __restrict__ out) {
    __shared__ unsigned sg[NNEUR * 4];   // transposed gate: sg[q*256+n]
    int tid = threadIdx.x;
    for (int q = tid; q < NNEUR * 4; q += 256) sg[q] = g_gate[q];
    __syncthreads();

    unsigned i = blockIdx.x * 256u + tid;
    uint4 s = g_sbits[i];
    unsigned w0 = s.x & sg[0 * NNEUR + tid];
    unsigned w1 = s.y & sg[1 * NNEUR + tid];
    unsigned w2 = s.z & sg[2 * NNEUR + tid];
    unsigned w3 = s.w & sg[3 * NNEUR + tid];

    float* o = out + (size_t)i * TT;
    while (w0) { int b = __ffs(w0) - 1; w0 &= w0 - 1; o[b] = 1.0f; }
    while (w1) { int b = __ffs(w1) - 1; w1 &= w1 - 1; o[32 + b] = 1.0f; }
    while (w2) { int b = __ffs(w2) - 1; w2 &= w2 - 1; o[64 + b] = 1.0f; }
    while (w3) { int b = __ffs(w3) - 1; w3 &= w3 - 1; o[96 + b] = 1.0f; }
}

extern "C" void kernel_launch(void* const* d_in, const int* in_sizes, int n_in,
                              void* d_out, int out_size) {
    (void)in_sizes; (void)n_in; (void)out_size;
    const float* x       = (const float*)d_in[0];
    const float* centers = (const float*)d_in[1];
    const float* widths  = (const float*)d_in[2];
    const float* adapt   = (const float*)d_in[3];
    const float* refr    = (const float*)d_in[4];
    const int*   seed    = (const int*)d_in[5];
    float* out = (float*)d_out;

    k_init  <<<1, 256>>>(seed);
    k_rng   <<<1024, 256>>>(x, centers, widths, adapt, out);
    k_scan  <<<1, NNEUR>>>(refr);
    k_sparse<<<2048, 256>>>(out);
}